// round 9
// baseline (speedup 1.0000x reference)
#include <cuda_runtime.h>
#include <cuda_bf16.h>
#include <math.h>
#include <stdint.h>

#define T_TOK 4096
#define E_DIM 1024
#define B_SZ  4
#define NSTEP 128

// ---------------- persistent device scratch ---------------------------------
__device__ float g_M[64 * 64];
__device__ float g_state[B_SZ * 32 * E_DIM];
__device__ float g_mu[256];
__device__ float g_rstd[256];
__device__ float g_res2[B_SZ * 64 * E_DIM];
__device__ __nv_bfloat16 g_ahi[256 * 1024];     // LN2 activations hi
__device__ __nv_bfloat16 g_alo[256 * 1024];     // lo residual
__device__ __nv_bfloat16 g_fhi[256 * 4096];     // sin(gate)*val hi
__device__ __nv_bfloat16 g_flo[256 * 4096];
__device__ __nv_bfloat16 g_wuphi[8192 * 1024];  // pair-interleaved w_up hi
__device__ __nv_bfloat16 g_wuplo[8192 * 1024];
__device__ __nv_bfloat16 g_wdnhi[1024 * 4096];
__device__ __nv_bfloat16 g_wdnlo[1024 * 4096];
__device__ float g_opart[8 * 256 * 1024];
__device__ int g_cnt[16];                       // split-K semaphores (zero-init)

// ---------------- helpers ----------------------------------------------------
__device__ __forceinline__ uint32_t smem_u32(const void* p) {
    uint32_t a;
    asm("{ .reg .u64 t; cvta.to.shared.u64 t, %1; cvt.u32.u64 %0, t; }" : "=r"(a) : "l"(p));
    return a;
}
#define CP_ASYNC16(dst, src) \
    asm volatile("cp.async.cg.shared.global [%0], [%1], 16;" :: "r"(dst), "l"(src))
#define CP_COMMIT() asm volatile("cp.async.commit_group;" ::: "memory")
#define CP_WAIT2()  asm volatile("cp.async.wait_group 2;" ::: "memory")

__device__ __forceinline__ float warp_sum(float v) {
#pragma unroll
    for (int m = 16; m > 0; m >>= 1) v += __shfl_xor_sync(0xffffffffu, v, m);
    return v;
}

// ---------------- init kernels -----------------------------------------------
__global__ void k_init_M(const float* __restrict__ wf1, const float* __restrict__ wf2) {
    int idx = blockIdx.x * 256 + threadIdx.x;
    int t = idx >> 6, tp = idx & 63;
    float s = 0.f;
#pragma unroll 8
    for (int u = 0; u < 48; u++) s = fmaf(wf2[t * 48 + u], wf1[u * 64 + tp], s);
    g_M[idx] = s;
}
__global__ void k_init_state(const float* __restrict__ x) {
    int idx = (blockIdx.x * 256 + threadIdx.x) * 4;
    int b = idx >> 15, r = idx & 32767;
    *(float4*)(g_state + idx) = *(const float4*)(x + ((size_t)b << 22) + r);
}
// pair-interleave: dst row n: nt=n>>7, i=n&127: even i -> gate nt*64+i/2, odd -> val
__global__ void k_conv_wup(const float* __restrict__ w) {
    int n = blockIdx.x, tid = threadIdx.x;
    int nt = n >> 7, i = n & 127;
    int src = (i & 1) ? (4096 + nt * 64 + (i >> 1)) : (nt * 64 + (i >> 1));
    const float* sp = w + ((size_t)src << 10);
    int c = tid * 4;
    float4 v = *(const float4*)(sp + c);
    __nv_bfloat16 h0 = __float2bfloat16(v.x), h1 = __float2bfloat16(v.y);
    __nv_bfloat16 h2 = __float2bfloat16(v.z), h3 = __float2bfloat16(v.w);
    __nv_bfloat16 l0 = __float2bfloat16(v.x - __bfloat162float(h0));
    __nv_bfloat16 l1 = __float2bfloat16(v.y - __bfloat162float(h1));
    __nv_bfloat16 l2 = __float2bfloat16(v.z - __bfloat162float(h2));
    __nv_bfloat16 l3 = __float2bfloat16(v.w - __bfloat162float(h3));
    size_t o = ((size_t)n << 10) + c;
    *(__nv_bfloat162*)(g_wuphi + o) = __halves2bfloat162(h0, h1);
    *(__nv_bfloat162*)(g_wuphi + o + 2) = __halves2bfloat162(h2, h3);
    *(__nv_bfloat162*)(g_wuplo + o) = __halves2bfloat162(l0, l1);
    *(__nv_bfloat162*)(g_wuplo + o + 2) = __halves2bfloat162(l2, l3);
}
__global__ void k_conv_wdn(const float* __restrict__ w) {
    int e = blockIdx.x, tid = threadIdx.x;
    const float* sp = w + (size_t)e * 4096;
#pragma unroll
    for (int j = 0; j < 4; j++) {
        int c = (j * 256 + tid) * 4;
        float4 v = *(const float4*)(sp + c);
        __nv_bfloat16 h0 = __float2bfloat16(v.x), h1 = __float2bfloat16(v.y);
        __nv_bfloat16 h2 = __float2bfloat16(v.z), h3 = __float2bfloat16(v.w);
        __nv_bfloat16 l0 = __float2bfloat16(v.x - __bfloat162float(h0));
        __nv_bfloat16 l1 = __float2bfloat16(v.y - __bfloat162float(h1));
        __nv_bfloat16 l2 = __float2bfloat16(v.z - __bfloat162float(h2));
        __nv_bfloat16 l3 = __float2bfloat16(v.w - __bfloat162float(h3));
        size_t o = (size_t)e * 4096 + c;
        *(__nv_bfloat162*)(g_wdnhi + o) = __halves2bfloat162(h0, h1);
        *(__nv_bfloat162*)(g_wdnhi + o + 2) = __halves2bfloat162(h2, h3);
        *(__nv_bfloat162*)(g_wdnlo + o) = __halves2bfloat162(l0, l1);
        *(__nv_bfloat162*)(g_wdnlo + o + 2) = __halves2bfloat162(l2, l3);
    }
}

// ---------------- step kernel 1: LN1 row stats only --------------------------
__global__ __launch_bounds__(256) void k_stats(const float* __restrict__ x, int step) {
    int t = blockIdx.x, b = blockIdx.y, tid = threadIdx.x;
    float4 vv = make_float4(0.f, 0.f, 0.f, 0.f);
    if (t < 32) {
        vv = *(const float4*)(g_state + ((b * 32 + t) << 10) + tid * 4);
    } else {
        int tok = step * 32 + t;
        if (tok < T_TOK)
            vv = *(const float4*)(x + ((size_t)(b * T_TOK + tok) << 10) + tid * 4);
    }
    float s = vv.x + vv.y + vv.z + vv.w;
    float q = vv.x * vv.x + vv.y * vv.y + vv.z * vv.z + vv.w * vv.w;
    __shared__ float rs[8], rq[8];
    s = warp_sum(s); q = warp_sum(q);
    int wid = tid >> 5;
    if ((tid & 31) == 0) { rs[wid] = s; rq[wid] = q; }
    __syncthreads();
    if (tid == 0) {
        float S = 0.f, Q = 0.f;
#pragma unroll
        for (int i = 0; i < 8; i++) { S += rs[i]; Q += rq[i]; }
        float mu = S * (1.f / 1024.f);
        g_mu[b * 64 + t] = mu;
        g_rstd[b * 64 + t] = rsqrtf(Q * (1.f / 1024.f) - mu * mu + 1e-5f);
    }
}

// ---------------- step kernel 2: folded LN1 + fft + res2 + LN2 + split -------
// fft[t,e] = w1[e]*(sum_tp c[tp]*v[tp,e] - off) + b1[e]*S ; c=M*rstd
__global__ __launch_bounds__(256) void k_fft(const float* __restrict__ x,
                                             const float* __restrict__ ln1w,
                                             const float* __restrict__ ln1b,
                                             const float* __restrict__ ln2w,
                                             const float* __restrict__ ln2b, int step) {
    int t = blockIdx.x, b = blockIdx.y, tid = threadIdx.x;
    __shared__ float sc[64], spo[64], sps[64];
    __shared__ float s_off, s_S;
    __shared__ float rs[8], rq[8], smu, srstd;
    if (tid < 64) {
        float m = (tid <= t) ? g_M[t * 64 + tid] : 0.f;
        float r = g_rstd[b * 64 + tid];
        float mu = g_mu[b * 64 + tid];
        float c = m * r;
        sc[tid] = c;
        spo[tid] = c * mu;
        sps[tid] = m;
    }
    __syncthreads();
    if (tid == 0) {
        float po = 0.f, ps = 0.f;
#pragma unroll
        for (int i = 0; i < 64; i++) { po += spo[i]; ps += sps[i]; }
        s_off = po; s_S = ps;
    }
    __syncthreads();
    int e0 = tid * 4;
    float4 acc = make_float4(0.f, 0.f, 0.f, 0.f);
    int lim1 = (t < 32) ? t : 31;
    for (int tp = 0; tp <= lim1; tp++) {
        float c = sc[tp];
        float4 v = *(const float4*)(g_state + ((b * 32 + tp) << 10) + e0);
        acc.x = fmaf(c, v.x, acc.x); acc.y = fmaf(c, v.y, acc.y);
        acc.z = fmaf(c, v.z, acc.z); acc.w = fmaf(c, v.w, acc.w);
    }
    int hi = t;
    int vmax = T_TOK - step * 32 - 1;
    if (hi > vmax) hi = vmax;
    for (int tp = 32; tp <= hi; tp++) {
        float c = sc[tp];
        int tok = step * 32 + tp;
        float4 v = *(const float4*)(x + ((size_t)(b * T_TOK + tok) << 10) + e0);
        acc.x = fmaf(c, v.x, acc.x); acc.y = fmaf(c, v.y, acc.y);
        acc.z = fmaf(c, v.z, acc.z); acc.w = fmaf(c, v.w, acc.w);
    }
    float off = s_off, S = s_S;
    float4 w1 = *(const float4*)(ln1w + e0);
    float4 b1 = *(const float4*)(ln1b + e0);
    int tok_t = step * 32 + t;
    float4 cv = make_float4(0.f, 0.f, 0.f, 0.f);
    if (tok_t < T_TOK)
        cv = *(const float4*)(x + ((size_t)(b * T_TOK + tok_t) << 10) + e0);
    float4 r2;
    r2.x = w1.x * (acc.x - off) + b1.x * S + cv.x;
    r2.y = w1.y * (acc.y - off) + b1.y * S + cv.y;
    r2.z = w1.z * (acc.z - off) + b1.z * S + cv.z;
    r2.w = w1.w * (acc.w - off) + b1.w * S + cv.w;
    int gm = b * 64 + t;
    *(float4*)(g_res2 + ((size_t)gm << 10) + e0) = r2;
    float s = r2.x + r2.y + r2.z + r2.w;
    float q = r2.x * r2.x + r2.y * r2.y + r2.z * r2.z + r2.w * r2.w;
    s = warp_sum(s); q = warp_sum(q);
    int wid = tid >> 5;
    if ((tid & 31) == 0) { rs[wid] = s; rq[wid] = q; }
    __syncthreads();
    if (tid == 0) {
        float S2 = 0.f, Q2 = 0.f;
#pragma unroll
        for (int i = 0; i < 8; i++) { S2 += rs[i]; Q2 += rq[i]; }
        float mu = S2 * (1.f / 1024.f);
        smu = mu;
        srstd = rsqrtf(Q2 * (1.f / 1024.f) - mu * mu + 1e-5f);
    }
    __syncthreads();
    float mu = smu, rstd = srstd;
    float4 wv = *(const float4*)(ln2w + e0);
    float4 bv = *(const float4*)(ln2b + e0);
    float a0 = (r2.x - mu) * rstd * wv.x + bv.x;
    float a1 = (r2.y - mu) * rstd * wv.y + bv.y;
    float a2 = (r2.z - mu) * rstd * wv.z + bv.z;
    float a3 = (r2.w - mu) * rstd * wv.w + bv.w;
    __nv_bfloat16 h0 = __float2bfloat16(a0), h1 = __float2bfloat16(a1);
    __nv_bfloat16 h2 = __float2bfloat16(a2), h3 = __float2bfloat16(a3);
    __nv_bfloat16 l0 = __float2bfloat16(a0 - __bfloat162float(h0));
    __nv_bfloat16 l1 = __float2bfloat16(a1 - __bfloat162float(h1));
    __nv_bfloat16 l2 = __float2bfloat16(a2 - __bfloat162float(h2));
    __nv_bfloat16 l3 = __float2bfloat16(a3 - __bfloat162float(h3));
    size_t o = ((size_t)gm << 10) + e0;
    *(__nv_bfloat162*)(g_ahi + o) = __halves2bfloat162(h0, h1);
    *(__nv_bfloat162*)(g_ahi + o + 2) = __halves2bfloat162(h2, h3);
    *(__nv_bfloat162*)(g_alo + o) = __halves2bfloat162(l0, l1);
    *(__nv_bfloat162*)(g_alo + o + 2) = __halves2bfloat162(l2, l3);
}

// ---------------- GEMM core --------------------------------------------------
// tile 128x128, BK=32; 4-stage ring; stage = {Ahi, Alo, Bhi, Blo}; 3 passes
#define PITCH 40
#define TILE_B (128 * PITCH * 2)    // 10240
#define STG4 (4 * TILE_B)           // 40960 per stage
#define NSTG 4
#define SMEM_TOT (NSTG * STG4)      // 163840

__device__ __forceinline__ void load_tile32(uint32_t sbase,
                                            const __nv_bfloat16* __restrict__ P,
                                            int r0, int k0, int pitch, int tid) {
#pragma unroll
    for (int i = 0; i < 2; i++) {
        int u = i * 256 + tid;
        int row = u >> 2, c16 = u & 3;
        const void* src = P + (size_t)(r0 + row) * pitch + k0 + c16 * 8;
        CP_ASYNC16(sbase + (row * PITCH + c16 * 8) * 2, src);
    }
}
__device__ __forceinline__ void load_stage32(uint32_t sbase,
                                             const __nv_bfloat16* Ahi, const __nv_bfloat16* Alo,
                                             const __nv_bfloat16* Bhi, const __nv_bfloat16* Blo,
                                             int m0, int n0, int k0, int ap, int bp, int tid) {
    load_tile32(sbase,              Ahi, m0, k0, ap, tid);
    load_tile32(sbase + TILE_B,     Alo, m0, k0, ap, tid);
    load_tile32(sbase + 2 * TILE_B, Bhi, n0, k0, bp, tid);
    load_tile32(sbase + 3 * TILE_B, Blo, n0, k0, bp, tid);
}

#define MMA(acc, a, b0, b1) \
    asm volatile("mma.sync.aligned.m16n8k16.row.col.f32.bf16.bf16.f32 " \
        "{%0,%1,%2,%3}, {%4,%5,%6,%7}, {%8,%9}, {%0,%1,%2,%3};" \
        : "+f"((acc)[0]), "+f"((acc)[1]), "+f"((acc)[2]), "+f"((acc)[3]) \
        : "r"((a)[0]), "r"((a)[1]), "r"((a)[2]), "r"((a)[3]), "r"(b0), "r"(b1))

__device__ __forceinline__ void compute_chunk32(uint32_t sbase, int wm, int wn, int lane,
                                                float acc[4][4][4]) {
    uint32_t sAhi = sbase, sAlo = sbase + TILE_B;
    uint32_t sBhi = sbase + 2 * TILE_B, sBlo = sbase + 3 * TILE_B;
#pragma unroll
    for (int kk = 0; kk < 2; kk++) {
        uint32_t ahi[4][4], alo[4][4], bhi[2][4], blo[2][4];
#pragma unroll
        for (int mt = 0; mt < 4; mt++) {
            uint32_t off = ((wm * 64 + mt * 16 + (lane & 15)) * PITCH
                            + kk * 16 + (lane >> 4) * 8) * 2;
            asm volatile("ldmatrix.sync.aligned.m8n8.x4.shared.b16 {%0,%1,%2,%3}, [%4];"
                : "=r"(ahi[mt][0]), "=r"(ahi[mt][1]), "=r"(ahi[mt][2]), "=r"(ahi[mt][3])
                : "r"(sAhi + off));
            asm volatile("ldmatrix.sync.aligned.m8n8.x4.shared.b16 {%0,%1,%2,%3}, [%4];"
                : "=r"(alo[mt][0]), "=r"(alo[mt][1]), "=r"(alo[mt][2]), "=r"(alo[mt][3])
                : "r"(sAlo + off));
        }
#pragma unroll
        for (int nb = 0; nb < 2; nb++) {
            uint32_t off = ((wn * 32 + nb * 16 + (lane & 15)) * PITCH
                            + kk * 16 + (lane >> 4) * 8) * 2;
            asm volatile("ldmatrix.sync.aligned.m8n8.x4.shared.b16 {%0,%1,%2,%3}, [%4];"
                : "=r"(bhi[nb][0]), "=r"(bhi[nb][1]), "=r"(bhi[nb][2]), "=r"(bhi[nb][3])
                : "r"(sBhi + off));
            asm volatile("ldmatrix.sync.aligned.m8n8.x4.shared.b16 {%0,%1,%2,%3}, [%4];"
                : "=r"(blo[nb][0]), "=r"(blo[nb][1]), "=r"(blo[nb][2]), "=r"(blo[nb][3])
                : "r"(sBlo + off));
        }
#pragma unroll
        for (int mt = 0; mt < 4; mt++)
#pragma unroll
            for (int nt = 0; nt < 4; nt++) {
                int hb = nt >> 1, lb = nt & 1;
                MMA(acc[mt][nt], ahi[mt], bhi[hb][lb], bhi[hb][2 + lb]);
                MMA(acc[mt][nt], alo[mt], bhi[hb][lb], bhi[hb][2 + lb]);
                MMA(acc[mt][nt], ahi[mt], blo[hb][lb], blo[hb][2 + lb]);
            }
    }
}

// ---------------- GEMM1 ------------------------------------------------------
// grid (64, 2), block 256
__global__ __launch_bounds__(256) void k_gemm1(const float* __restrict__ b_up) {
    extern __shared__ char smem[];
    uint32_t sb = smem_u32(smem);
    int tid = threadIdx.x, lane = tid & 31, wid = tid >> 5;
    int wm = wid & 1, wn = wid >> 1;
    int bx = blockIdx.x, by = blockIdx.y;
    float acc[4][4][4];
#pragma unroll
    for (int i = 0; i < 4; i++)
#pragma unroll
        for (int j = 0; j < 4; j++)
#pragma unroll
            for (int k = 0; k < 4; k++) acc[i][j][k] = 0.f;

    const int C = 32;
#pragma unroll
    for (int p = 0; p < 3; p++) {
        load_stage32(sb + p * STG4, g_ahi, g_alo, g_wuphi, g_wuplo,
                     by * 128, bx * 128, p * 32, 1024, 1024, tid);
        CP_COMMIT();
    }
    for (int c = 0; c < C; c++) {
        CP_WAIT2();
        __syncthreads();
        if (c + 3 < C)
            load_stage32(sb + ((c + 3) & 3) * STG4, g_ahi, g_alo, g_wuphi, g_wuplo,
                         by * 128, bx * 128, (c + 3) * 32, 1024, 1024, tid);
        CP_COMMIT();
        compute_chunk32(sb + (c & 3) * STG4, wm, wn, lane, acc);
    }

#pragma unroll
    for (int mt = 0; mt < 4; mt++) {
        int r0 = by * 128 + wm * 64 + mt * 16 + (lane >> 2);
#pragma unroll
        for (int nt = 0; nt < 4; nt++) {
            int fc = bx * 64 + wn * 16 + nt * 4 + (lane & 3);
            float bg = b_up[fc], bv = b_up[4096 + fc];
            float f0 = sinf(acc[mt][nt][0] + bg) * (acc[mt][nt][1] + bv);
            float f1 = sinf(acc[mt][nt][2] + bg) * (acc[mt][nt][3] + bv);
            size_t o0 = (size_t)r0 * 4096 + fc;
            size_t o1 = o0 + (size_t)8 * 4096;
            __nv_bfloat16 h0 = __float2bfloat16(f0);
            g_fhi[o0] = h0;
            g_flo[o0] = __float2bfloat16(f0 - __bfloat162float(h0));
            __nv_bfloat16 h1 = __float2bfloat16(f1);
            g_fhi[o1] = h1;
            g_flo[o1] = __float2bfloat16(f1 - __bfloat162float(h1));
        }
    }
}

// ---------------- GEMM2 + fused split-K finisher -----------------------------
// grid (8, 2, 8), block 256
__global__ __launch_bounds__(256) void k_gemm2(const float* __restrict__ b_down,
                                               float* __restrict__ out, int step) {
    extern __shared__ char smem[];
    uint32_t sb = smem_u32(smem);
    int tid = threadIdx.x, lane = tid & 31, wid = tid >> 5;
    int wm = wid & 1, wn = wid >> 1;
    int bx = blockIdx.x, by = blockIdx.y, bz = blockIdx.z;
    float acc[4][4][4];
#pragma unroll
    for (int i = 0; i < 4; i++)
#pragma unroll
        for (int j = 0; j < 4; j++)
#pragma unroll
            for (int k = 0; k < 4; k++) acc[i][j][k] = 0.f;

    const int C = 16;
#pragma unroll
    for (int p = 0; p < 3; p++) {
        load_stage32(sb + p * STG4, g_fhi, g_flo, g_wdnhi, g_wdnlo,
                     by * 128, bx * 128, bz * 512 + p * 32, 4096, 4096, tid);
        CP_COMMIT();
    }
    for (int c = 0; c < C; c++) {
        CP_WAIT2();
        __syncthreads();
        if (c + 3 < C)
            load_stage32(sb + ((c + 3) & 3) * STG4, g_fhi, g_flo, g_wdnhi, g_wdnlo,
                         by * 128, bx * 128, bz * 512 + (c + 3) * 32, 4096, 4096, tid);
        CP_COMMIT();
        compute_chunk32(sb + (c & 3) * STG4, wm, wn, lane, acc);
    }

#pragma unroll
    for (int mt = 0; mt < 4; mt++) {
        int r0 = by * 128 + wm * 64 + mt * 16 + (lane >> 2);
#pragma unroll
        for (int nt = 0; nt < 4; nt++) {
            int col = bx * 128 + wn * 32 + nt * 8 + (lane & 3) * 2;
            float* op = g_opart + ((size_t)(bz * 256) + r0) * 1024 + col;
            *(float2*)op = make_float2(acc[mt][nt][0], acc[mt][nt][1]);
            *(float2*)(op + (size_t)8 * 1024) = make_float2(acc[mt][nt][2], acc[mt][nt][3]);
        }
    }

    // ---- split-K finisher: 8th-arriving CTA per (bx,by) reduces ----
    __threadfence();
    __shared__ int s_last;
    if (tid == 0) {
        int old;
        asm volatile("atom.add.release.gpu.s32 %0, [%1], 1;"
                     : "=r"(old) : "l"(&g_cnt[by * 8 + bx]) : "memory");
        s_last = (old == 7);
    }
    __syncthreads();
    if (s_last) {
        __threadfence();
#pragma unroll
        for (int i = 0; i < 16; i++) {
            int u = i * 256 + tid;
            int r = u >> 5, c4 = (u & 31) * 4;
            int gm = by * 128 + r;
            int col = bx * 128 + c4;
            float4 a = *(const float4*)(g_opart + ((size_t)gm << 10) + col);
#pragma unroll
            for (int s = 1; s < 8; s++) {
                float4 p = *(const float4*)(g_opart + ((size_t)((s << 8) + gm) << 10) + col);
                a.x += p.x; a.y += p.y; a.z += p.z; a.w += p.w;
            }
            float4 bd = *(const float4*)(b_down + col);
            float4 r2 = *(const float4*)(g_res2 + ((size_t)gm << 10) + col);
            a.x += bd.x + r2.x; a.y += bd.y + r2.y;
            a.z += bd.z + r2.z; a.w += bd.w + r2.w;
            int b = gm >> 6, t = gm & 63;
            float* dst = (t < 32)
                ? out + ((size_t)(b * T_TOK + step * 32 + t) << 10) + col
                : g_state + ((b * 32 + (t - 32)) << 10) + col;
            *(float4*)dst = a;
        }
        __syncthreads();
        if (tid == 0) g_cnt[by * 8 + bx] = 0;
    }
}

// ---------------- host launcher ----------------------------------------------
extern "C" void kernel_launch(void* const* d_in, const int* in_sizes, int n_in,
                              void* d_out, int out_size) {
    const float* x    = (const float*)d_in[0];
    const float* ln1w = (const float*)d_in[1];
    const float* ln1b = (const float*)d_in[2];
    const float* wf1  = (const float*)d_in[3];
    const float* wf2  = (const float*)d_in[4];
    const float* ln2w = (const float*)d_in[5];
    const float* ln2b = (const float*)d_in[6];
    const float* w_up = (const float*)d_in[7];
    const float* b_up = (const float*)d_in[8];
    const float* w_dn = (const float*)d_in[9];
    const float* b_dn = (const float*)d_in[10];
    float* out = (float*)d_out;

    cudaFuncSetAttribute(k_gemm1, cudaFuncAttributeMaxDynamicSharedMemorySize, SMEM_TOT);
    cudaFuncSetAttribute(k_gemm2, cudaFuncAttributeMaxDynamicSharedMemorySize, SMEM_TOT);

    k_init_M<<<16, 256>>>(wf1, wf2);
    k_init_state<<<128, 256>>>(x);
    k_conv_wup<<<8192, 256>>>(w_up);
    k_conv_wdn<<<1024, 256>>>(w_dn);

    for (int i = 0; i < NSTEP; i++) {
        k_stats<<<dim3(64, 4), 256>>>(x, i);
        k_fft<<<dim3(64, 4), 256>>>(x, ln1w, ln1b, ln2w, ln2b, i);
        k_gemm1<<<dim3(64, 2), 256, SMEM_TOT>>>(b_up);
        k_gemm2<<<dim3(8, 2, 8), 256, SMEM_TOT>>>(b_dn, out, i);
    }
}

// round 12
// speedup vs baseline: 1.0393x; 1.0393x over previous
#include <cuda_runtime.h>
#include <cuda_bf16.h>
#include <math.h>
#include <stdint.h>

#define T_TOK 4096
#define E_DIM 1024
#define B_SZ  4
#define NSTEP 128
#define XPAD  4160   // 4096 + 64

// ---------------- persistent device scratch ---------------------------------
__device__ float g_M[64 * 64];
__device__ float g_state[B_SZ * 32 * E_DIM];
__device__ float g_xmu[B_SZ][XPAD];
__device__ float g_xrstd[B_SZ][XPAD];
__device__ float g_spart[256][8][2];            // state-row LN1 partials per bx
__device__ float g_res2[B_SZ * 64 * E_DIM];
__device__ __nv_bfloat16 g_ahi[256 * 1024];
__device__ __nv_bfloat16 g_alo[256 * 1024];
__device__ __nv_bfloat16 g_fhi[256 * 4096];
__device__ __nv_bfloat16 g_flo[256 * 4096];
__device__ __nv_bfloat16 g_wuphi[8192 * 1024];
__device__ __nv_bfloat16 g_wuplo[8192 * 1024];
__device__ __nv_bfloat16 g_wdnhi[1024 * 4096];
__device__ __nv_bfloat16 g_wdnlo[1024 * 4096];
__device__ float g_opart[8 * 256 * 1024];
__device__ int g_cnt[16];

// ---------------- helpers ----------------------------------------------------
__device__ __forceinline__ uint32_t smem_u32(const void* p) {
    uint32_t a;
    asm("{ .reg .u64 t; cvta.to.shared.u64 t, %1; cvt.u32.u64 %0, t; }" : "=r"(a) : "l"(p));
    return a;
}
#define CP_ASYNC16(dst, src) \
    asm volatile("cp.async.cg.shared.global [%0], [%1], 16;" :: "r"(dst), "l"(src))
#define CP_COMMIT() asm volatile("cp.async.commit_group;" ::: "memory")
#define CP_WAIT1()  asm volatile("cp.async.wait_group 1;" ::: "memory")

__device__ __forceinline__ float warp_sum(float v) {
#pragma unroll
    for (int m = 16; m > 0; m >>= 1) v += __shfl_xor_sync(0xffffffffu, v, m);
    return v;
}

// ---------------- init kernels -----------------------------------------------
__global__ void k_init_M(const float* __restrict__ wf1, const float* __restrict__ wf2) {
    int idx = blockIdx.x * 256 + threadIdx.x;
    int t = idx >> 6, tp = idx & 63;
    float s = 0.f;
#pragma unroll 8
    for (int u = 0; u < 48; u++) s = fmaf(wf2[t * 48 + u], wf1[u * 64 + tp], s);
    g_M[idx] = s;
}
__global__ void k_init_state(const float* __restrict__ x) {
    int idx = (blockIdx.x * 256 + threadIdx.x) * 4;
    int b = idx >> 15, r = idx & 32767;
    *(float4*)(g_state + idx) = *(const float4*)(x + ((size_t)b << 22) + r);
}
// LN1 stats for every x token (padded region -> zero-row stats), one-time
__global__ __launch_bounds__(256) void k_xstats(const float* __restrict__ x) {
    int tok = blockIdx.x, b = blockIdx.y, tid = threadIdx.x;
    float4 vv = make_float4(0.f, 0.f, 0.f, 0.f);
    if (tok < T_TOK)
        vv = *(const float4*)(x + ((size_t)(b * T_TOK + tok) << 10) + tid * 4);
    float s = vv.x + vv.y + vv.z + vv.w;
    float q = vv.x * vv.x + vv.y * vv.y + vv.z * vv.z + vv.w * vv.w;
    __shared__ float rs[8], rq[8];
    s = warp_sum(s); q = warp_sum(q);
    int wid = tid >> 5;
    if ((tid & 31) == 0) { rs[wid] = s; rq[wid] = q; }
    __syncthreads();
    if (tid == 0) {
        float S = 0.f, Q = 0.f;
#pragma unroll
        for (int i = 0; i < 8; i++) { S += rs[i]; Q += rq[i]; }
        float mu = S * (1.f / 1024.f);
        g_xmu[b][tok] = mu;
        g_xrstd[b][tok] = rsqrtf(Q * (1.f / 1024.f) - mu * mu + 1e-5f);
    }
}
__global__ void k_conv_wup(const float* __restrict__ w) {
    int n = blockIdx.x, tid = threadIdx.x;
    int nt = n >> 7, i = n & 127;
    int src = (i & 1) ? (4096 + nt * 64 + (i >> 1)) : (nt * 64 + (i >> 1));
    const float* sp = w + ((size_t)src << 10);
    int c = tid * 4;
    float4 v = *(const float4*)(sp + c);
    __nv_bfloat16 h0 = __float2bfloat16(v.x), h1 = __float2bfloat16(v.y);
    __nv_bfloat16 h2 = __float2bfloat16(v.z), h3 = __float2bfloat16(v.w);
    __nv_bfloat16 l0 = __float2bfloat16(v.x - __bfloat162float(h0));
    __nv_bfloat16 l1 = __float2bfloat16(v.y - __bfloat162float(h1));
    __nv_bfloat16 l2 = __float2bfloat16(v.z - __bfloat162float(h2));
    __nv_bfloat16 l3 = __float2bfloat16(v.w - __bfloat162float(h3));
    size_t o = ((size_t)n << 10) + c;
    *(__nv_bfloat162*)(g_wuphi + o) = __halves2bfloat162(h0, h1);
    *(__nv_bfloat162*)(g_wuphi + o + 2) = __halves2bfloat162(h2, h3);
    *(__nv_bfloat162*)(g_wuplo + o) = __halves2bfloat162(l0, l1);
    *(__nv_bfloat162*)(g_wuplo + o + 2) = __halves2bfloat162(l2, l3);
}
__global__ void k_conv_wdn(const float* __restrict__ w) {
    int e = blockIdx.x, tid = threadIdx.x;
    const float* sp = w + (size_t)e * 4096;
#pragma unroll
    for (int j = 0; j < 4; j++) {
        int c = (j * 256 + tid) * 4;
        float4 v = *(const float4*)(sp + c);
        __nv_bfloat16 h0 = __float2bfloat16(v.x), h1 = __float2bfloat16(v.y);
        __nv_bfloat16 h2 = __float2bfloat16(v.z), h3 = __float2bfloat16(v.w);
        __nv_bfloat16 l0 = __float2bfloat16(v.x - __bfloat162float(h0));
        __nv_bfloat16 l1 = __float2bfloat16(v.y - __bfloat162float(h1));
        __nv_bfloat16 l2 = __float2bfloat16(v.z - __bfloat162float(h2));
        __nv_bfloat16 l3 = __float2bfloat16(v.w - __bfloat162float(h3));
        size_t o = (size_t)e * 4096 + c;
        *(__nv_bfloat162*)(g_wdnhi + o) = __halves2bfloat162(h0, h1);
        *(__nv_bfloat162*)(g_wdnhi + o + 2) = __halves2bfloat162(h2, h3);
        *(__nv_bfloat162*)(g_wdnlo + o) = __halves2bfloat162(l0, l1);
        *(__nv_bfloat162*)(g_wdnlo + o + 2) = __halves2bfloat162(l2, l3);
    }
}

// ---------------- step kernel: folded LN1 + fft + res2 + LN2 + split ---------
__global__ __launch_bounds__(256) void k_fft(const float* __restrict__ x,
                                             const float* __restrict__ ln1w,
                                             const float* __restrict__ ln1b,
                                             const float* __restrict__ ln2w,
                                             const float* __restrict__ ln2b, int step) {
    int t = blockIdx.x, b = blockIdx.y, tid = threadIdx.x;
    __shared__ float sc[64], spo[64], sps[64];
    __shared__ float s_off, s_S;
    __shared__ float rs[8], rq[8], smu, srstd;
    if (tid < 64) {
        float mu, r;
        if (tid < 32) {                       // state rows
            if (step == 0) {
                mu = g_xmu[b][tid]; r = g_xrstd[b][tid];
            } else {
                int gm = b * 64 + 32 + tid;   // prev-step output row that became state
                float S = 0.f, Q = 0.f;
#pragma unroll
                for (int c = 0; c < 8; c++) { S += g_spart[gm][c][0]; Q += g_spart[gm][c][1]; }
                mu = S * (1.f / 1024.f);
                r = rsqrtf(Q * (1.f / 1024.f) - mu * mu + 1e-5f);
            }
        } else {                              // x rows (padded table)
            int tok = step * 32 + tid;
            mu = g_xmu[b][tok]; r = g_xrstd[b][tok];
        }
        float m = (tid <= t) ? g_M[t * 64 + tid] : 0.f;
        float c = m * r;
        sc[tid] = c;
        spo[tid] = c * mu;
        sps[tid] = m;
    }
    __syncthreads();
    if (tid == 0) {
        float po = 0.f, ps = 0.f;
#pragma unroll
        for (int i = 0; i < 64; i++) { po += spo[i]; ps += sps[i]; }
        s_off = po; s_S = ps;
    }
    __syncthreads();
    int e0 = tid * 4;
    float4 acc = make_float4(0.f, 0.f, 0.f, 0.f);
    int lim1 = (t < 32) ? t : 31;
    for (int tp = 0; tp <= lim1; tp++) {
        float c = sc[tp];
        float4 v = *(const float4*)(g_state + ((b * 32 + tp) << 10) + e0);
        acc.x = fmaf(c, v.x, acc.x); acc.y = fmaf(c, v.y, acc.y);
        acc.z = fmaf(c, v.z, acc.z); acc.w = fmaf(c, v.w, acc.w);
    }
    int hi = t;
    int vmax = T_TOK - step * 32 - 1;
    if (hi > vmax) hi = vmax;
    for (int tp = 32; tp <= hi; tp++) {
        float c = sc[tp];
        int tok = step * 32 + tp;
        float4 v = *(const float4*)(x + ((size_t)(b * T_TOK + tok) << 10) + e0);
        acc.x = fmaf(c, v.x, acc.x); acc.y = fmaf(c, v.y, acc.y);
        acc.z = fmaf(c, v.z, acc.z); acc.w = fmaf(c, v.w, acc.w);
    }
    float off = s_off, S = s_S;
    float4 w1 = *(const float4*)(ln1w + e0);
    float4 b1 = *(const float4*)(ln1b + e0);
    int tok_t = step * 32 + t;
    float4 cv = make_float4(0.f, 0.f, 0.f, 0.f);
    if (tok_t < T_TOK)
        cv = *(const float4*)(x + ((size_t)(b * T_TOK + tok_t) << 10) + e0);
    float4 r2;
    r2.x = w1.x * (acc.x - off) + b1.x * S + cv.x;
    r2.y = w1.y * (acc.y - off) + b1.y * S + cv.y;
    r2.z = w1.z * (acc.z - off) + b1.z * S + cv.z;
    r2.w = w1.w * (acc.w - off) + b1.w * S + cv.w;
    int gm = b * 64 + t;
    *(float4*)(g_res2 + ((size_t)gm << 10) + e0) = r2;
    float s = r2.x + r2.y + r2.z + r2.w;
    float q = r2.x * r2.x + r2.y * r2.y + r2.z * r2.z + r2.w * r2.w;
    s = warp_sum(s); q = warp_sum(q);
    int wid = tid >> 5;
    if ((tid & 31) == 0) { rs[wid] = s; rq[wid] = q; }
    __syncthreads();
    if (tid == 0) {
        float S2 = 0.f, Q2 = 0.f;
#pragma unroll
        for (int i = 0; i < 8; i++) { S2 += rs[i]; Q2 += rq[i]; }
        float mu = S2 * (1.f / 1024.f);
        smu = mu;
        srstd = rsqrtf(Q2 * (1.f / 1024.f) - mu * mu + 1e-5f);
    }
    __syncthreads();
    float mu = smu, rstd = srstd;
    float4 wv = *(const float4*)(ln2w + e0);
    float4 bv = *(const float4*)(ln2b + e0);
    float a0 = (r2.x - mu) * rstd * wv.x + bv.x;
    float a1 = (r2.y - mu) * rstd * wv.y + bv.y;
    float a2 = (r2.z - mu) * rstd * wv.z + bv.z;
    float a3 = (r2.w - mu) * rstd * wv.w + bv.w;
    __nv_bfloat16 h0 = __float2bfloat16(a0), h1 = __float2bfloat16(a1);
    __nv_bfloat16 h2 = __float2bfloat16(a2), h3 = __float2bfloat16(a3);
    __nv_bfloat16 l0 = __float2bfloat16(a0 - __bfloat162float(h0));
    __nv_bfloat16 l1 = __float2bfloat16(a1 - __bfloat162float(h1));
    __nv_bfloat16 l2 = __float2bfloat16(a2 - __bfloat162float(h2));
    __nv_bfloat16 l3 = __float2bfloat16(a3 - __bfloat162float(h3));
    size_t o = ((size_t)gm << 10) + e0;
    *(__nv_bfloat162*)(g_ahi + o) = __halves2bfloat162(h0, h1);
    *(__nv_bfloat162*)(g_ahi + o + 2) = __halves2bfloat162(h2, h3);
    *(__nv_bfloat162*)(g_alo + o) = __halves2bfloat162(l0, l1);
    *(__nv_bfloat162*)(g_alo + o + 2) = __halves2bfloat162(l2, l3);
}

// ---------------- GEMM core (exact R8 config): BK=64, 2-stage, 3 passes ------
#define PITCH 72
#define TILE_B (128 * PITCH * 2)    // 18432
#define STG4 (4 * TILE_B)           // 73728 per stage
#define SMEM_TOT (2 * STG4)         // 147456

__device__ __forceinline__ void load_tile(uint32_t sbase,
                                          const __nv_bfloat16* __restrict__ P,
                                          int r0, int k0, int pitch, int tid) {
#pragma unroll
    for (int i = 0; i < 4; i++) {
        int u = i * 256 + tid;
        int row = u >> 3, c16 = u & 7;
        const void* src = P + (size_t)(r0 + row) * pitch + k0 + c16 * 8;
        CP_ASYNC16(sbase + (row * PITCH + c16 * 8) * 2, src);
    }
}
__device__ __forceinline__ void load_stage4(uint32_t sbase,
                                            const __nv_bfloat16* Ahi, const __nv_bfloat16* Alo,
                                            const __nv_bfloat16* Bhi, const __nv_bfloat16* Blo,
                                            int m0, int n0, int k0, int ap, int bp, int tid) {
    load_tile(sbase,              Ahi, m0, k0, ap, tid);
    load_tile(sbase + TILE_B,     Alo, m0, k0, ap, tid);
    load_tile(sbase + 2 * TILE_B, Bhi, n0, k0, bp, tid);
    load_tile(sbase + 3 * TILE_B, Blo, n0, k0, bp, tid);
}

#define MMA(acc, a, b0, b1) \
    asm volatile("mma.sync.aligned.m16n8k16.row.col.f32.bf16.bf16.f32 " \
        "{%0,%1,%2,%3}, {%4,%5,%6,%7}, {%8,%9}, {%0,%1,%2,%3};" \
        : "+f"((acc)[0]), "+f"((acc)[1]), "+f"((acc)[2]), "+f"((acc)[3]) \
        : "r"((a)[0]), "r"((a)[1]), "r"((a)[2]), "r"((a)[3]), "r"(b0), "r"(b1))

__device__ __forceinline__ void compute_chunk(uint32_t sbase, int wm, int wn, int lane,
                                              float acc[4][4][4]) {
    uint32_t sAhi = sbase, sAlo = sbase + TILE_B;
    uint32_t sBhi = sbase + 2 * TILE_B, sBlo = sbase + 3 * TILE_B;
#pragma unroll
    for (int kk = 0; kk < 4; kk++) {
        uint32_t ahi[4][4], alo[4][4], bhi[2][4], blo[2][4];
#pragma unroll
        for (int mt = 0; mt < 4; mt++) {
            uint32_t off = ((wm * 64 + mt * 16 + (lane & 15)) * PITCH
                            + kk * 16 + (lane >> 4) * 8) * 2;
            asm volatile("ldmatrix.sync.aligned.m8n8.x4.shared.b16 {%0,%1,%2,%3}, [%4];"
                : "=r"(ahi[mt][0]), "=r"(ahi[mt][1]), "=r"(ahi[mt][2]), "=r"(ahi[mt][3])
                : "r"(sAhi + off));
            asm volatile("ldmatrix.sync.aligned.m8n8.x4.shared.b16 {%0,%1,%2,%3}, [%4];"
                : "=r"(alo[mt][0]), "=r"(alo[mt][1]), "=r"(alo[mt][2]), "=r"(alo[mt][3])
                : "r"(sAlo + off));
        }
#pragma unroll
        for (int nb = 0; nb < 2; nb++) {
            uint32_t off = ((wn * 32 + nb * 16 + (lane & 15)) * PITCH
                            + kk * 16 + (lane >> 4) * 8) * 2;
            asm volatile("ldmatrix.sync.aligned.m8n8.x4.shared.b16 {%0,%1,%2,%3}, [%4];"
                : "=r"(bhi[nb][0]), "=r"(bhi[nb][1]), "=r"(bhi[nb][2]), "=r"(bhi[nb][3])
                : "r"(sBhi + off));
            asm volatile("ldmatrix.sync.aligned.m8n8.x4.shared.b16 {%0,%1,%2,%3}, [%4];"
                : "=r"(blo[nb][0]), "=r"(blo[nb][1]), "=r"(blo[nb][2]), "=r"(blo[nb][3])
                : "r"(sBlo + off));
        }
#pragma unroll
        for (int mt = 0; mt < 4; mt++)
#pragma unroll
            for (int nt = 0; nt < 4; nt++) {
                int hb = nt >> 1, lb = nt & 1;
                MMA(acc[mt][nt], ahi[mt], bhi[hb][lb], bhi[hb][2 + lb]);
                MMA(acc[mt][nt], alo[mt], bhi[hb][lb], bhi[hb][2 + lb]);
                MMA(acc[mt][nt], ahi[mt], blo[hb][lb], blo[hb][2 + lb]);
            }
    }
}

// ---------------- GEMM1 ------------------------------------------------------
// grid (64, 2), block 256
__global__ __launch_bounds__(256) void k_gemm1(const float* __restrict__ b_up) {
    extern __shared__ char smem[];
    uint32_t sb = smem_u32(smem);
    int tid = threadIdx.x, lane = tid & 31, wid = tid >> 5;
    int wm = wid & 1, wn = wid >> 1;
    int bx = blockIdx.x, by = blockIdx.y;
    float acc[4][4][4];
#pragma unroll
    for (int i = 0; i < 4; i++)
#pragma unroll
        for (int j = 0; j < 4; j++)
#pragma unroll
            for (int k = 0; k < 4; k++) acc[i][j][k] = 0.f;

    const int C = 16;
    load_stage4(sb, g_ahi, g_alo, g_wuphi, g_wuplo, by * 128, bx * 128, 0, 1024, 1024, tid);
    CP_COMMIT();
    for (int c = 0; c < C; c++) {
        if (c + 1 < C)
            load_stage4(sb + ((c + 1) & 1) * STG4, g_ahi, g_alo, g_wuphi, g_wuplo,
                        by * 128, bx * 128, (c + 1) * 64, 1024, 1024, tid);
        CP_COMMIT();
        CP_WAIT1();
        __syncthreads();
        compute_chunk(sb + (c & 1) * STG4, wm, wn, lane, acc);
        __syncthreads();
    }

#pragma unroll
    for (int mt = 0; mt < 4; mt++) {
        int r0 = by * 128 + wm * 64 + mt * 16 + (lane >> 2);
#pragma unroll
        for (int nt = 0; nt < 4; nt++) {
            int fc = bx * 64 + wn * 16 + nt * 4 + (lane & 3);
            float bg = b_up[fc], bv = b_up[4096 + fc];
            float f0 = sinf(acc[mt][nt][0] + bg) * (acc[mt][nt][1] + bv);
            float f1 = sinf(acc[mt][nt][2] + bg) * (acc[mt][nt][3] + bv);
            size_t o0 = (size_t)r0 * 4096 + fc;
            size_t o1 = o0 + (size_t)8 * 4096;
            __nv_bfloat16 h0 = __float2bfloat16(f0);
            g_fhi[o0] = h0;
            g_flo[o0] = __float2bfloat16(f0 - __bfloat162float(h0));
            __nv_bfloat16 h1 = __float2bfloat16(f1);
            g_fhi[o1] = h1;
            g_flo[o1] = __float2bfloat16(f1 - __bfloat162float(h1));
        }
    }
}

// ---------------- GEMM2 + fused finisher (+state LN1 partials) ---------------
// grid (8, 2, 8), block 256
__global__ __launch_bounds__(256) void k_gemm2(const float* __restrict__ b_down,
                                               float* __restrict__ out, int step) {
    extern __shared__ char smem[];
    uint32_t sb = smem_u32(smem);
    int tid = threadIdx.x, lane = tid & 31, wid = tid >> 5;
    int wm = wid & 1, wn = wid >> 1;
    int bx = blockIdx.x, by = blockIdx.y, bz = blockIdx.z;
    float acc[4][4][4];
#pragma unroll
    for (int i = 0; i < 4; i++)
#pragma unroll
        for (int j = 0; j < 4; j++)
#pragma unroll
            for (int k = 0; k < 4; k++) acc[i][j][k] = 0.f;

    const int C = 8;
    load_stage4(sb, g_fhi, g_flo, g_wdnhi, g_wdnlo,
                by * 128, bx * 128, bz * 512, 4096, 4096, tid);
    CP_COMMIT();
    for (int c = 0; c < C; c++) {
        if (c + 1 < C)
            load_stage4(sb + ((c + 1) & 1) * STG4, g_fhi, g_flo, g_wdnhi, g_wdnlo,
                        by * 128, bx * 128, bz * 512 + (c + 1) * 64, 4096, 4096, tid);
        CP_COMMIT();
        CP_WAIT1();
        __syncthreads();
        compute_chunk(sb + (c & 1) * STG4, wm, wn, lane, acc);
        __syncthreads();
    }

#pragma unroll
    for (int mt = 0; mt < 4; mt++) {
        int r0 = by * 128 + wm * 64 + mt * 16 + (lane >> 2);
#pragma unroll
        for (int nt = 0; nt < 4; nt++) {
            int col = bx * 128 + wn * 32 + nt * 8 + (lane & 3) * 2;
            float* op = g_opart + ((size_t)(bz * 256) + r0) * 1024 + col;
            *(float2*)op = make_float2(acc[mt][nt][0], acc[mt][nt][1]);
            *(float2*)(op + (size_t)8 * 1024) = make_float2(acc[mt][nt][2], acc[mt][nt][3]);
        }
    }

    // ---- split-K finisher: 8th-arriving CTA per (bx,by) ----
    __threadfence();
    __shared__ int s_last;
    if (tid == 0) {
        int old;
        asm volatile("atom.add.release.gpu.s32 %0, [%1], 1;"
                     : "=r"(old) : "l"(&g_cnt[by * 8 + bx]) : "memory");
        s_last = (old == 7);
    }
    __syncthreads();
    if (s_last) {
        __threadfence();
#pragma unroll
        for (int i = 0; i < 16; i++) {
            int u = i * 256 + tid;
            int r = u >> 5, c4 = (u & 31) * 4;
            int gm = by * 128 + r;
            int col = bx * 128 + c4;
            float4 a = *(const float4*)(g_opart + ((size_t)gm << 10) + col);
#pragma unroll
            for (int s = 1; s < 8; s++) {
                float4 p = *(const float4*)(g_opart + ((size_t)((s << 8) + gm) << 10) + col);
                a.x += p.x; a.y += p.y; a.z += p.z; a.w += p.w;
            }
            float4 bd = *(const float4*)(b_down + col);
            float4 r2 = *(const float4*)(g_res2 + ((size_t)gm << 10) + col);
            a.x += bd.x + r2.x; a.y += bd.y + r2.y;
            a.z += bd.z + r2.z; a.w += bd.w + r2.w;
            int b = gm >> 6, t = gm & 63;
            float* dst = (t < 32)
                ? out + ((size_t)(b * T_TOK + step * 32 + t) << 10) + col
                : g_state + ((b * 32 + (t - 32)) << 10) + col;
            *(float4*)dst = a;
            // LN1 partial stats for rows that become next step's state
            float s = a.x + a.y + a.z + a.w;
            float q = a.x * a.x + a.y * a.y + a.z * a.z + a.w * a.w;
            s = warp_sum(s); q = warp_sum(q);
            if ((tid & 31) == 0) {
                g_spart[gm][bx][0] = s;
                g_spart[gm][bx][1] = q;
            }
        }
        __syncthreads();
        if (tid == 0) g_cnt[by * 8 + bx] = 0;
    }
}

// ---------------- host launcher ----------------------------------------------
extern "C" void kernel_launch(void* const* d_in, const int* in_sizes, int n_in,
                              void* d_out, int out_size) {
    const float* x    = (const float*)d_in[0];
    const float* ln1w = (const float*)d_in[1];
    const float* ln1b = (const float*)d_in[2];
    const float* wf1  = (const float*)d_in[3];
    const float* wf2  = (const float*)d_in[4];
    const float* ln2w = (const float*)d_in[5];
    const float* ln2b = (const float*)d_in[6];
    const float* w_up = (const float*)d_in[7];
    const float* b_up = (const float*)d_in[8];
    const float* w_dn = (const float*)d_in[9];
    const float* b_dn = (const float*)d_in[10];
    float* out = (float*)d_out;

    cudaFuncSetAttribute(k_gemm1, cudaFuncAttributeMaxDynamicSharedMemorySize, SMEM_TOT);
    cudaFuncSetAttribute(k_gemm2, cudaFuncAttributeMaxDynamicSharedMemorySize, SMEM_TOT);

    k_init_M<<<16, 256>>>(wf1, wf2);
    k_init_state<<<128, 256>>>(x);
    k_xstats<<<dim3(XPAD, B_SZ), 256>>>(x);
    k_conv_wup<<<8192, 256>>>(w_up);
    k_conv_wdn<<<1024, 256>>>(w_dn);

    for (int i = 0; i < NSTEP; i++) {
        k_fft<<<dim3(64, 4), 256>>>(x, ln1w, ln1b, ln2w, ln2b, i);
        k_gemm1<<<dim3(64, 2), 256, SMEM_TOT>>>(b_up);
        k_gemm2<<<dim3(8, 2, 8), 256, SMEM_TOT>>>(b_dn, out, i);
    }
}

// round 13
// speedup vs baseline: 1.3032x; 1.2540x over previous
#include <cuda_runtime.h>
#include <cuda_fp16.h>
#include <math.h>
#include <stdint.h>

#define T_TOK 4096
#define E_DIM 1024
#define B_SZ  4
#define NSTEP 128
#define XPAD  4160   // 4096 + 64

// ---------------- persistent device scratch ---------------------------------
__device__ float g_M[64 * 64];
__device__ float g_state[B_SZ * 32 * E_DIM];
__device__ float g_xmu[B_SZ][XPAD];
__device__ float g_xrstd[B_SZ][XPAD];
__device__ float g_spart[256][8][2];            // state-row LN1 partials per bx
__device__ float g_res2[B_SZ * 64 * E_DIM];
__device__ __half g_ahi[256 * 1024];            // LN2 activations hi (fp16)
__device__ __half g_alo[256 * 1024];            // lo residual (fp16)
__device__ __half g_fhi[256 * 4096];
__device__ __half g_flo[256 * 4096];
__device__ __half g_wuphi[8192 * 1024];         // pair-interleaved w_up (fp16, hi only)
__device__ __half g_wdnhi[1024 * 4096];         // w_down (fp16, hi only)
__device__ float g_opart[8 * 256 * 1024];
__device__ int g_cnt[16];

// ---------------- helpers ----------------------------------------------------
__device__ __forceinline__ uint32_t smem_u32(const void* p) {
    uint32_t a;
    asm("{ .reg .u64 t; cvta.to.shared.u64 t, %1; cvt.u32.u64 %0, t; }" : "=r"(a) : "l"(p));
    return a;
}
#define CP_ASYNC16(dst, src) \
    asm volatile("cp.async.cg.shared.global [%0], [%1], 16;" :: "r"(dst), "l"(src))
#define CP_COMMIT() asm volatile("cp.async.commit_group;" ::: "memory")
#define CP_WAIT1()  asm volatile("cp.async.wait_group 1;" ::: "memory")

__device__ __forceinline__ float warp_sum(float v) {
#pragma unroll
    for (int m = 16; m > 0; m >>= 1) v += __shfl_xor_sync(0xffffffffu, v, m);
    return v;
}

// ---------------- init kernels -----------------------------------------------
__global__ void k_init_M(const float* __restrict__ wf1, const float* __restrict__ wf2) {
    int idx = blockIdx.x * 256 + threadIdx.x;
    int t = idx >> 6, tp = idx & 63;
    float s = 0.f;
#pragma unroll 8
    for (int u = 0; u < 48; u++) s = fmaf(wf2[t * 48 + u], wf1[u * 64 + tp], s);
    g_M[idx] = s;
}
__global__ void k_init_state(const float* __restrict__ x) {
    int idx = (blockIdx.x * 256 + threadIdx.x) * 4;
    int b = idx >> 15, r = idx & 32767;
    *(float4*)(g_state + idx) = *(const float4*)(x + ((size_t)b << 22) + r);
}
// LN1 stats for every x token (padded region -> zero-row stats), one-time
__global__ __launch_bounds__(256) void k_xstats(const float* __restrict__ x) {
    int tok = blockIdx.x, b = blockIdx.y, tid = threadIdx.x;
    float4 vv = make_float4(0.f, 0.f, 0.f, 0.f);
    if (tok < T_TOK)
        vv = *(const float4*)(x + ((size_t)(b * T_TOK + tok) << 10) + tid * 4);
    float s = vv.x + vv.y + vv.z + vv.w;
    float q = vv.x * vv.x + vv.y * vv.y + vv.z * vv.z + vv.w * vv.w;
    __shared__ float rs[8], rq[8];
    s = warp_sum(s); q = warp_sum(q);
    int wid = tid >> 5;
    if ((tid & 31) == 0) { rs[wid] = s; rq[wid] = q; }
    __syncthreads();
    if (tid == 0) {
        float S = 0.f, Q = 0.f;
#pragma unroll
        for (int i = 0; i < 8; i++) { S += rs[i]; Q += rq[i]; }
        float mu = S * (1.f / 1024.f);
        g_xmu[b][tok] = mu;
        g_xrstd[b][tok] = rsqrtf(Q * (1.f / 1024.f) - mu * mu + 1e-5f);
    }
}
// pair-interleave: dst row n: nt=n>>7, i=n&127: even i -> gate nt*64+i/2, odd -> val
__global__ void k_conv_wup(const float* __restrict__ w) {
    int n = blockIdx.x, tid = threadIdx.x;
    int nt = n >> 7, i = n & 127;
    int src = (i & 1) ? (4096 + nt * 64 + (i >> 1)) : (nt * 64 + (i >> 1));
    const float* sp = w + ((size_t)src << 10);
    int c = tid * 4;
    float4 v = *(const float4*)(sp + c);
    size_t o = ((size_t)n << 10) + c;
    *(__half2*)(g_wuphi + o) = __halves2half2(__float2half(v.x), __float2half(v.y));
    *(__half2*)(g_wuphi + o + 2) = __halves2half2(__float2half(v.z), __float2half(v.w));
}
__global__ void k_conv_wdn(const float* __restrict__ w) {
    int e = blockIdx.x, tid = threadIdx.x;
    const float* sp = w + (size_t)e * 4096;
#pragma unroll
    for (int j = 0; j < 4; j++) {
        int c = (j * 256 + tid) * 4;
        float4 v = *(const float4*)(sp + c);
        size_t o = (size_t)e * 4096 + c;
        *(__half2*)(g_wdnhi + o) = __halves2half2(__float2half(v.x), __float2half(v.y));
        *(__half2*)(g_wdnhi + o + 2) = __halves2half2(__float2half(v.z), __float2half(v.w));
    }
}

// ---------------- step kernel: folded LN1 + fft + res2 + LN2 + split ---------
__global__ __launch_bounds__(256) void k_fft(const float* __restrict__ x,
                                             const float* __restrict__ ln1w,
                                             const float* __restrict__ ln1b,
                                             const float* __restrict__ ln2w,
                                             const float* __restrict__ ln2b, int step) {
    int t = blockIdx.x, b = blockIdx.y, tid = threadIdx.x;
    __shared__ float sc[64], spo[64], sps[64];
    __shared__ float s_off, s_S;
    __shared__ float rs[8], rq[8], smu, srstd;
    if (tid < 64) {
        float mu, r;
        if (tid < 32) {                       // state rows
            if (step == 0) {
                mu = g_xmu[b][tid]; r = g_xrstd[b][tid];
            } else {
                int gm = b * 64 + 32 + tid;   // prev-step output row that became state
                float S = 0.f, Q = 0.f;
#pragma unroll
                for (int c = 0; c < 8; c++) { S += g_spart[gm][c][0]; Q += g_spart[gm][c][1]; }
                mu = S * (1.f / 1024.f);
                r = rsqrtf(Q * (1.f / 1024.f) - mu * mu + 1e-5f);
            }
        } else {                              // x rows (padded table)
            int tok = step * 32 + tid;
            mu = g_xmu[b][tok]; r = g_xrstd[b][tok];
        }
        float m = (tid <= t) ? g_M[t * 64 + tid] : 0.f;
        float c = m * r;
        sc[tid] = c;
        spo[tid] = c * mu;
        sps[tid] = m;
    }
    __syncthreads();
    if (tid == 0) {
        float po = 0.f, ps = 0.f;
#pragma unroll
        for (int i = 0; i < 64; i++) { po += spo[i]; ps += sps[i]; }
        s_off = po; s_S = ps;
    }
    __syncthreads();
    int e0 = tid * 4;
    float4 acc = make_float4(0.f, 0.f, 0.f, 0.f);
    int lim1 = (t < 32) ? t : 31;
    for (int tp = 0; tp <= lim1; tp++) {
        float c = sc[tp];
        float4 v = *(const float4*)(g_state + ((b * 32 + tp) << 10) + e0);
        acc.x = fmaf(c, v.x, acc.x); acc.y = fmaf(c, v.y, acc.y);
        acc.z = fmaf(c, v.z, acc.z); acc.w = fmaf(c, v.w, acc.w);
    }
    int hi = t;
    int vmax = T_TOK - step * 32 - 1;
    if (hi > vmax) hi = vmax;
    for (int tp = 32; tp <= hi; tp++) {
        float c = sc[tp];
        int tok = step * 32 + tp;
        float4 v = *(const float4*)(x + ((size_t)(b * T_TOK + tok) << 10) + e0);
        acc.x = fmaf(c, v.x, acc.x); acc.y = fmaf(c, v.y, acc.y);
        acc.z = fmaf(c, v.z, acc.z); acc.w = fmaf(c, v.w, acc.w);
    }
    float off = s_off, S = s_S;
    float4 w1 = *(const float4*)(ln1w + e0);
    float4 b1 = *(const float4*)(ln1b + e0);
    int tok_t = step * 32 + t;
    float4 cv = make_float4(0.f, 0.f, 0.f, 0.f);
    if (tok_t < T_TOK)
        cv = *(const float4*)(x + ((size_t)(b * T_TOK + tok_t) << 10) + e0);
    float4 r2;
    r2.x = w1.x * (acc.x - off) + b1.x * S + cv.x;
    r2.y = w1.y * (acc.y - off) + b1.y * S + cv.y;
    r2.z = w1.z * (acc.z - off) + b1.z * S + cv.z;
    r2.w = w1.w * (acc.w - off) + b1.w * S + cv.w;
    int gm = b * 64 + t;
    *(float4*)(g_res2 + ((size_t)gm << 10) + e0) = r2;
    float s = r2.x + r2.y + r2.z + r2.w;
    float q = r2.x * r2.x + r2.y * r2.y + r2.z * r2.z + r2.w * r2.w;
    s = warp_sum(s); q = warp_sum(q);
    int wid = tid >> 5;
    if ((tid & 31) == 0) { rs[wid] = s; rq[wid] = q; }
    __syncthreads();
    if (tid == 0) {
        float S2 = 0.f, Q2 = 0.f;
#pragma unroll
        for (int i = 0; i < 8; i++) { S2 += rs[i]; Q2 += rq[i]; }
        float mu = S2 * (1.f / 1024.f);
        smu = mu;
        srstd = rsqrtf(Q2 * (1.f / 1024.f) - mu * mu + 1e-5f);
    }
    __syncthreads();
    float mu = smu, rstd = srstd;
    float4 wv = *(const float4*)(ln2w + e0);
    float4 bv = *(const float4*)(ln2b + e0);
    float a0 = (r2.x - mu) * rstd * wv.x + bv.x;
    float a1 = (r2.y - mu) * rstd * wv.y + bv.y;
    float a2 = (r2.z - mu) * rstd * wv.z + bv.z;
    float a3 = (r2.w - mu) * rstd * wv.w + bv.w;
    __half h0 = __float2half(a0), h1 = __float2half(a1);
    __half h2 = __float2half(a2), h3 = __float2half(a3);
    __half l0 = __float2half(a0 - __half2float(h0));
    __half l1 = __float2half(a1 - __half2float(h1));
    __half l2 = __float2half(a2 - __half2float(h2));
    __half l3 = __float2half(a3 - __half2float(h3));
    size_t o = ((size_t)gm << 10) + e0;
    *(__half2*)(g_ahi + o) = __halves2half2(h0, h1);
    *(__half2*)(g_ahi + o + 2) = __halves2half2(h2, h3);
    *(__half2*)(g_alo + o) = __halves2half2(l0, l1);
    *(__half2*)(g_alo + o + 2) = __halves2half2(l2, l3);
}

// ---------------- GEMM core: BK=64, 2-stage, 2 fp16 passes -------------------
// stage = {Ahi, Alo, Bhi}; a·b ≈ (ahi+alo)·bhi
#define PITCH 72
#define TILE_B (128 * PITCH * 2)    // 18432
#define STG3 (3 * TILE_B)           // 55296 per stage
#define SMEM_TOT (2 * STG3)         // 110592

__device__ __forceinline__ void load_tile(uint32_t sbase,
                                          const __half* __restrict__ P,
                                          int r0, int k0, int pitch, int tid) {
#pragma unroll
    for (int i = 0; i < 4; i++) {
        int u = i * 256 + tid;
        int row = u >> 3, c16 = u & 7;
        const void* src = P + (size_t)(r0 + row) * pitch + k0 + c16 * 8;
        CP_ASYNC16(sbase + (row * PITCH + c16 * 8) * 2, src);
    }
}
__device__ __forceinline__ void load_stage3(uint32_t sbase,
                                            const __half* Ahi, const __half* Alo,
                                            const __half* Bhi,
                                            int m0, int n0, int k0, int ap, int bp, int tid) {
    load_tile(sbase,              Ahi, m0, k0, ap, tid);
    load_tile(sbase + TILE_B,     Alo, m0, k0, ap, tid);
    load_tile(sbase + 2 * TILE_B, Bhi, n0, k0, bp, tid);
}

#define MMA(acc, a, b0, b1) \
    asm volatile("mma.sync.aligned.m16n8k16.row.col.f32.f16.f16.f32 " \
        "{%0,%1,%2,%3}, {%4,%5,%6,%7}, {%8,%9}, {%0,%1,%2,%3};" \
        : "+f"((acc)[0]), "+f"((acc)[1]), "+f"((acc)[2]), "+f"((acc)[3]) \
        : "r"((a)[0]), "r"((a)[1]), "r"((a)[2]), "r"((a)[3]), "r"(b0), "r"(b1))

__device__ __forceinline__ void compute_chunk(uint32_t sbase, int wm, int wn, int lane,
                                              float acc[4][4][4]) {
    uint32_t sAhi = sbase, sAlo = sbase + TILE_B;
    uint32_t sBhi = sbase + 2 * TILE_B;
#pragma unroll
    for (int kk = 0; kk < 4; kk++) {
        uint32_t ahi[4][4], alo[4][4], bhi[2][4];
#pragma unroll
        for (int mt = 0; mt < 4; mt++) {
            uint32_t off = ((wm * 64 + mt * 16 + (lane & 15)) * PITCH
                            + kk * 16 + (lane >> 4) * 8) * 2;
            asm volatile("ldmatrix.sync.aligned.m8n8.x4.shared.b16 {%0,%1,%2,%3}, [%4];"
                : "=r"(ahi[mt][0]), "=r"(ahi[mt][1]), "=r"(ahi[mt][2]), "=r"(ahi[mt][3])
                : "r"(sAhi + off));
            asm volatile("ldmatrix.sync.aligned.m8n8.x4.shared.b16 {%0,%1,%2,%3}, [%4];"
                : "=r"(alo[mt][0]), "=r"(alo[mt][1]), "=r"(alo[mt][2]), "=r"(alo[mt][3])
                : "r"(sAlo + off));
        }
#pragma unroll
        for (int nb = 0; nb < 2; nb++) {
            uint32_t off = ((wn * 32 + nb * 16 + (lane & 15)) * PITCH
                            + kk * 16 + (lane >> 4) * 8) * 2;
            asm volatile("ldmatrix.sync.aligned.m8n8.x4.shared.b16 {%0,%1,%2,%3}, [%4];"
                : "=r"(bhi[nb][0]), "=r"(bhi[nb][1]), "=r"(bhi[nb][2]), "=r"(bhi[nb][3])
                : "r"(sBhi + off));
        }
#pragma unroll
        for (int mt = 0; mt < 4; mt++)
#pragma unroll
            for (int nt = 0; nt < 4; nt++) {
                int hb = nt >> 1, lb = nt & 1;
                MMA(acc[mt][nt], ahi[mt], bhi[hb][lb], bhi[hb][2 + lb]);
                MMA(acc[mt][nt], alo[mt], bhi[hb][lb], bhi[hb][2 + lb]);
            }
    }
}

// ---------------- GEMM1 ------------------------------------------------------
// grid (64, 2), block 256
__global__ __launch_bounds__(256) void k_gemm1(const float* __restrict__ b_up) {
    extern __shared__ char smem[];
    uint32_t sb = smem_u32(smem);
    int tid = threadIdx.x, lane = tid & 31, wid = tid >> 5;
    int wm = wid & 1, wn = wid >> 1;
    int bx = blockIdx.x, by = blockIdx.y;
    float acc[4][4][4];
#pragma unroll
    for (int i = 0; i < 4; i++)
#pragma unroll
        for (int j = 0; j < 4; j++)
#pragma unroll
            for (int k = 0; k < 4; k++) acc[i][j][k] = 0.f;

    const int C = 16;
    load_stage3(sb, g_ahi, g_alo, g_wuphi, by * 128, bx * 128, 0, 1024, 1024, tid);
    CP_COMMIT();
    for (int c = 0; c < C; c++) {
        if (c + 1 < C)
            load_stage3(sb + ((c + 1) & 1) * STG3, g_ahi, g_alo, g_wuphi,
                        by * 128, bx * 128, (c + 1) * 64, 1024, 1024, tid);
        CP_COMMIT();
        CP_WAIT1();
        __syncthreads();
        compute_chunk(sb + (c & 1) * STG3, wm, wn, lane, acc);
        __syncthreads();
    }

#pragma unroll
    for (int mt = 0; mt < 4; mt++) {
        int r0 = by * 128 + wm * 64 + mt * 16 + (lane >> 2);
#pragma unroll
        for (int nt = 0; nt < 4; nt++) {
            int fc = bx * 64 + wn * 16 + nt * 4 + (lane & 3);
            float bg = b_up[fc], bv = b_up[4096 + fc];
            float f0 = sinf(acc[mt][nt][0] + bg) * (acc[mt][nt][1] + bv);
            float f1 = sinf(acc[mt][nt][2] + bg) * (acc[mt][nt][3] + bv);
            size_t o0 = (size_t)r0 * 4096 + fc;
            size_t o1 = o0 + (size_t)8 * 4096;
            __half h0 = __float2half(f0);
            g_fhi[o0] = h0;
            g_flo[o0] = __float2half(f0 - __half2float(h0));
            __half h1 = __float2half(f1);
            g_fhi[o1] = h1;
            g_flo[o1] = __float2half(f1 - __half2float(h1));
        }
    }
}

// ---------------- GEMM2 + fused finisher (+state LN1 partials) ---------------
// grid (8, 2, 8), block 256
__global__ __launch_bounds__(256) void k_gemm2(const float* __restrict__ b_down,
                                               float* __restrict__ out, int step) {
    extern __shared__ char smem[];
    uint32_t sb = smem_u32(smem);
    int tid = threadIdx.x, lane = tid & 31, wid = tid >> 5;
    int wm = wid & 1, wn = wid >> 1;
    int bx = blockIdx.x, by = blockIdx.y, bz = blockIdx.z;
    float acc[4][4][4];
#pragma unroll
    for (int i = 0; i < 4; i++)
#pragma unroll
        for (int j = 0; j < 4; j++)
#pragma unroll
            for (int k = 0; k < 4; k++) acc[i][j][k] = 0.f;

    const int C = 8;
    load_stage3(sb, g_fhi, g_flo, g_wdnhi,
                by * 128, bx * 128, bz * 512, 4096, 4096, tid);
    CP_COMMIT();
    for (int c = 0; c < C; c++) {
        if (c + 1 < C)
            load_stage3(sb + ((c + 1) & 1) * STG3, g_fhi, g_flo, g_wdnhi,
                        by * 128, bx * 128, bz * 512 + (c + 1) * 64, 4096, 4096, tid);
        CP_COMMIT();
        CP_WAIT1();
        __syncthreads();
        compute_chunk(sb + (c & 1) * STG3, wm, wn, lane, acc);
        __syncthreads();
    }

#pragma unroll
    for (int mt = 0; mt < 4; mt++) {
        int r0 = by * 128 + wm * 64 + mt * 16 + (lane >> 2);
#pragma unroll
        for (int nt = 0; nt < 4; nt++) {
            int col = bx * 128 + wn * 32 + nt * 8 + (lane & 3) * 2;
            float* op = g_opart + ((size_t)(bz * 256) + r0) * 1024 + col;
            *(float2*)op = make_float2(acc[mt][nt][0], acc[mt][nt][1]);
            *(float2*)(op + (size_t)8 * 1024) = make_float2(acc[mt][nt][2], acc[mt][nt][3]);
        }
    }

    // ---- split-K finisher: 8th-arriving CTA per (bx,by) ----
    __threadfence();
    __shared__ int s_last;
    if (tid == 0) {
        int old;
        asm volatile("atom.add.release.gpu.s32 %0, [%1], 1;"
                     : "=r"(old) : "l"(&g_cnt[by * 8 + bx]) : "memory");
        s_last = (old == 7);
    }
    __syncthreads();
    if (s_last) {
        __threadfence();
#pragma unroll
        for (int i = 0; i < 16; i++) {
            int u = i * 256 + tid;
            int r = u >> 5, c4 = (u & 31) * 4;
            int gm = by * 128 + r;
            int col = bx * 128 + c4;
            float4 a = *(const float4*)(g_opart + ((size_t)gm << 10) + col);
#pragma unroll
            for (int s = 1; s < 8; s++) {
                float4 p = *(const float4*)(g_opart + ((size_t)((s << 8) + gm) << 10) + col);
                a.x += p.x; a.y += p.y; a.z += p.z; a.w += p.w;
            }
            float4 bd = *(const float4*)(b_down + col);
            float4 r2 = *(const float4*)(g_res2 + ((size_t)gm << 10) + col);
            a.x += bd.x + r2.x; a.y += bd.y + r2.y;
            a.z += bd.z + r2.z; a.w += bd.w + r2.w;
            int b = gm >> 6, t = gm & 63;
            float* dst = (t < 32)
                ? out + ((size_t)(b * T_TOK + step * 32 + t) << 10) + col
                : g_state + ((b * 32 + (t - 32)) << 10) + col;
            *(float4*)dst = a;
            // LN1 partial stats for rows that become next step's state
            float s = a.x + a.y + a.z + a.w;
            float q = a.x * a.x + a.y * a.y + a.z * a.z + a.w * a.w;
            s = warp_sum(s); q = warp_sum(q);
            if ((tid & 31) == 0) {
                g_spart[gm][bx][0] = s;
                g_spart[gm][bx][1] = q;
            }
        }
        __syncthreads();
        if (tid == 0) g_cnt[by * 8 + bx] = 0;
    }
}

// ---------------- host launcher ----------------------------------------------
extern "C" void kernel_launch(void* const* d_in, const int* in_sizes, int n_in,
                              void* d_out, int out_size) {
    const float* x    = (const float*)d_in[0];
    const float* ln1w = (const float*)d_in[1];
    const float* ln1b = (const float*)d_in[2];
    const float* wf1  = (const float*)d_in[3];
    const float* wf2  = (const float*)d_in[4];
    const float* ln2w = (const float*)d_in[5];
    const float* ln2b = (const float*)d_in[6];
    const float* w_up = (const float*)d_in[7];
    const float* b_up = (const float*)d_in[8];
    const float* w_dn = (const float*)d_in[9];
    const float* b_dn = (const float*)d_in[10];
    float* out = (float*)d_out;

    cudaFuncSetAttribute(k_gemm1, cudaFuncAttributeMaxDynamicSharedMemorySize, SMEM_TOT);
    cudaFuncSetAttribute(k_gemm2, cudaFuncAttributeMaxDynamicSharedMemorySize, SMEM_TOT);

    k_init_M<<<16, 256>>>(wf1, wf2);
    k_init_state<<<128, 256>>>(x);
    k_xstats<<<dim3(XPAD, B_SZ), 256>>>(x);
    k_conv_wup<<<8192, 256>>>(w_up);
    k_conv_wdn<<<1024, 256>>>(w_dn);

    for (int i = 0; i < NSTEP; i++) {
        k_fft<<<dim3(64, 4), 256>>>(x, ln1w, ln1b, ln2w, ln2b, i);
        k_gemm1<<<dim3(64, 2), 256, SMEM_TOT>>>(b_up);
        k_gemm2<<<dim3(8, 2, 8), 256, SMEM_TOT>>>(b_dn, out, i);
    }
}

// round 14
// speedup vs baseline: 1.8589x; 1.4264x over previous
#include <cuda_runtime.h>
#include <cuda_fp16.h>
#include <math.h>
#include <stdint.h>

#define T_TOK 4096
#define E_DIM 1024
#define B_SZ  4
#define NSTEP 128
#define XPAD  4160   // 4096 + 64

// ---------------- persistent device scratch ---------------------------------
__device__ float g_M[64 * 64];
__device__ float g_state[B_SZ * 32 * E_DIM];
__device__ float g_xmu[B_SZ][XPAD];
__device__ float g_xrstd[B_SZ][XPAD];
__device__ float g_spart[256][8][2];            // state-row LN1 partials per bx
__device__ float g_res2[B_SZ * 64 * E_DIM];
__device__ __half g_ahi[256 * 1024];            // LN2 activations (fp16)
__device__ __half g_fhi[256 * 4096];            // sin(gate)*val (fp16)
__device__ __half g_wuphi[8192 * 1024];         // pair-interleaved w_up (fp16)
__device__ __half g_wdnhi[1024 * 4096];         // w_down (fp16)
__device__ float g_opart[8 * 256 * 1024];
__device__ int g_cnt[16];

// ---------------- helpers ----------------------------------------------------
__device__ __forceinline__ uint32_t smem_u32(const void* p) {
    uint32_t a;
    asm("{ .reg .u64 t; cvta.to.shared.u64 t, %1; cvt.u32.u64 %0, t; }" : "=r"(a) : "l"(p));
    return a;
}
#define CP_ASYNC16(dst, src) \
    asm volatile("cp.async.cg.shared.global [%0], [%1], 16;" :: "r"(dst), "l"(src))
#define CP_COMMIT() asm volatile("cp.async.commit_group;" ::: "memory")
#define CP_WAIT1()  asm volatile("cp.async.wait_group 1;" ::: "memory")

__device__ __forceinline__ float warp_sum(float v) {
#pragma unroll
    for (int m = 16; m > 0; m >>= 1) v += __shfl_xor_sync(0xffffffffu, v, m);
    return v;
}

// ---------------- init kernels -----------------------------------------------
__global__ void k_init_M(const float* __restrict__ wf1, const float* __restrict__ wf2) {
    int idx = blockIdx.x * 256 + threadIdx.x;
    int t = idx >> 6, tp = idx & 63;
    float s = 0.f;
#pragma unroll 8
    for (int u = 0; u < 48; u++) s = fmaf(wf2[t * 48 + u], wf1[u * 64 + tp], s);
    g_M[idx] = s;
}
__global__ void k_init_state(const float* __restrict__ x) {
    int idx = (blockIdx.x * 256 + threadIdx.x) * 4;
    int b = idx >> 15, r = idx & 32767;
    *(float4*)(g_state + idx) = *(const float4*)(x + ((size_t)b << 22) + r);
}
// LN1 stats for every x token (padded region -> zero-row stats), one-time
__global__ __launch_bounds__(256) void k_xstats(const float* __restrict__ x) {
    int tok = blockIdx.x, b = blockIdx.y, tid = threadIdx.x;
    float4 vv = make_float4(0.f, 0.f, 0.f, 0.f);
    if (tok < T_TOK)
        vv = *(const float4*)(x + ((size_t)(b * T_TOK + tok) << 10) + tid * 4);
    float s = vv.x + vv.y + vv.z + vv.w;
    float q = vv.x * vv.x + vv.y * vv.y + vv.z * vv.z + vv.w * vv.w;
    __shared__ float rs[8], rq[8];
    s = warp_sum(s); q = warp_sum(q);
    int wid = tid >> 5;
    if ((tid & 31) == 0) { rs[wid] = s; rq[wid] = q; }
    __syncthreads();
    if (tid == 0) {
        float S = 0.f, Q = 0.f;
#pragma unroll
        for (int i = 0; i < 8; i++) { S += rs[i]; Q += rq[i]; }
        float mu = S * (1.f / 1024.f);
        g_xmu[b][tok] = mu;
        g_xrstd[b][tok] = rsqrtf(Q * (1.f / 1024.f) - mu * mu + 1e-5f);
    }
}
// pair-interleave: dst row n: nt=n>>7, i=n&127: even i -> gate nt*64+i/2, odd -> val
__global__ void k_conv_wup(const float* __restrict__ w) {
    int n = blockIdx.x, tid = threadIdx.x;
    int nt = n >> 7, i = n & 127;
    int src = (i & 1) ? (4096 + nt * 64 + (i >> 1)) : (nt * 64 + (i >> 1));
    const float* sp = w + ((size_t)src << 10);
    int c = tid * 4;
    float4 v = *(const float4*)(sp + c);
    size_t o = ((size_t)n << 10) + c;
    *(__half2*)(g_wuphi + o) = __halves2half2(__float2half(v.x), __float2half(v.y));
    *(__half2*)(g_wuphi + o + 2) = __halves2half2(__float2half(v.z), __float2half(v.w));
}
__global__ void k_conv_wdn(const float* __restrict__ w) {
    int e = blockIdx.x, tid = threadIdx.x;
    const float* sp = w + (size_t)e * 4096;
#pragma unroll
    for (int j = 0; j < 4; j++) {
        int c = (j * 256 + tid) * 4;
        float4 v = *(const float4*)(sp + c);
        size_t o = (size_t)e * 4096 + c;
        *(__half2*)(g_wdnhi + o) = __halves2half2(__float2half(v.x), __float2half(v.y));
        *(__half2*)(g_wdnhi + o + 2) = __halves2half2(__float2half(v.z), __float2half(v.w));
    }
}

// ---------------- step kernel: folded LN1 + fft + res2 + LN2 -----------------
__global__ __launch_bounds__(256) void k_fft(const float* __restrict__ x,
                                             const float* __restrict__ ln1w,
                                             const float* __restrict__ ln1b,
                                             const float* __restrict__ ln2w,
                                             const float* __restrict__ ln2b, int step) {
    int t = blockIdx.x, b = blockIdx.y, tid = threadIdx.x;
    __shared__ float sc[64], spo[64], sps[64];
    __shared__ float s_off, s_S;
    __shared__ float rs[8], rq[8], smu, srstd;
    if (tid < 64) {
        float mu, r;
        if (tid < 32) {                       // state rows
            if (step == 0) {
                mu = g_xmu[b][tid]; r = g_xrstd[b][tid];
            } else {
                int gm = b * 64 + 32 + tid;   // prev-step output row that became state
                float S = 0.f, Q = 0.f;
#pragma unroll
                for (int c = 0; c < 8; c++) { S += g_spart[gm][c][0]; Q += g_spart[gm][c][1]; }
                mu = S * (1.f / 1024.f);
                r = rsqrtf(Q * (1.f / 1024.f) - mu * mu + 1e-5f);
            }
        } else {                              // x rows (padded table)
            int tok = step * 32 + tid;
            mu = g_xmu[b][tok]; r = g_xrstd[b][tok];
        }
        float m = (tid <= t) ? g_M[t * 64 + tid] : 0.f;
        float c = m * r;
        sc[tid] = c;
        spo[tid] = c * mu;
        sps[tid] = m;
    }
    __syncthreads();
    if (tid == 0) {
        float po = 0.f, ps = 0.f;
#pragma unroll
        for (int i = 0; i < 64; i++) { po += spo[i]; ps += sps[i]; }
        s_off = po; s_S = ps;
    }
    __syncthreads();
    int e0 = tid * 4;
    float4 acc = make_float4(0.f, 0.f, 0.f, 0.f);
    int lim1 = (t < 32) ? t : 31;
    for (int tp = 0; tp <= lim1; tp++) {
        float c = sc[tp];
        float4 v = *(const float4*)(g_state + ((b * 32 + tp) << 10) + e0);
        acc.x = fmaf(c, v.x, acc.x); acc.y = fmaf(c, v.y, acc.y);
        acc.z = fmaf(c, v.z, acc.z); acc.w = fmaf(c, v.w, acc.w);
    }
    int hi = t;
    int vmax = T_TOK - step * 32 - 1;
    if (hi > vmax) hi = vmax;
    for (int tp = 32; tp <= hi; tp++) {
        float c = sc[tp];
        int tok = step * 32 + tp;
        float4 v = *(const float4*)(x + ((size_t)(b * T_TOK + tok) << 10) + e0);
        acc.x = fmaf(c, v.x, acc.x); acc.y = fmaf(c, v.y, acc.y);
        acc.z = fmaf(c, v.z, acc.z); acc.w = fmaf(c, v.w, acc.w);
    }
    float off = s_off, S = s_S;
    float4 w1 = *(const float4*)(ln1w + e0);
    float4 b1 = *(const float4*)(ln1b + e0);
    int tok_t = step * 32 + t;
    float4 cv = make_float4(0.f, 0.f, 0.f, 0.f);
    if (tok_t < T_TOK)
        cv = *(const float4*)(x + ((size_t)(b * T_TOK + tok_t) << 10) + e0);
    float4 r2;
    r2.x = w1.x * (acc.x - off) + b1.x * S + cv.x;
    r2.y = w1.y * (acc.y - off) + b1.y * S + cv.y;
    r2.z = w1.z * (acc.z - off) + b1.z * S + cv.z;
    r2.w = w1.w * (acc.w - off) + b1.w * S + cv.w;
    int gm = b * 64 + t;
    *(float4*)(g_res2 + ((size_t)gm << 10) + e0) = r2;
    float s = r2.x + r2.y + r2.z + r2.w;
    float q = r2.x * r2.x + r2.y * r2.y + r2.z * r2.z + r2.w * r2.w;
    s = warp_sum(s); q = warp_sum(q);
    int wid = tid >> 5;
    if ((tid & 31) == 0) { rs[wid] = s; rq[wid] = q; }
    __syncthreads();
    if (tid == 0) {
        float S2 = 0.f, Q2 = 0.f;
#pragma unroll
        for (int i = 0; i < 8; i++) { S2 += rs[i]; Q2 += rq[i]; }
        float mu = S2 * (1.f / 1024.f);
        smu = mu;
        srstd = rsqrtf(Q2 * (1.f / 1024.f) - mu * mu + 1e-5f);
    }
    __syncthreads();
    float mu = smu, rstd = srstd;
    float4 wv = *(const float4*)(ln2w + e0);
    float4 bv = *(const float4*)(ln2b + e0);
    float a0 = (r2.x - mu) * rstd * wv.x + bv.x;
    float a1 = (r2.y - mu) * rstd * wv.y + bv.y;
    float a2 = (r2.z - mu) * rstd * wv.z + bv.z;
    float a3 = (r2.w - mu) * rstd * wv.w + bv.w;
    size_t o = ((size_t)gm << 10) + e0;
    *(__half2*)(g_ahi + o) = __halves2half2(__float2half(a0), __float2half(a1));
    *(__half2*)(g_ahi + o + 2) = __halves2half2(__float2half(a2), __float2half(a3));
}

// ---------------- GEMM core: BK=64, 2-stage, 1 fp16 pass ---------------------
#define PITCH 72
#define TILE_B (128 * PITCH * 2)    // 18432
#define STG2 (2 * TILE_B)           // 36864 per stage (A + B)
#define SMEM_TOT (2 * STG2)         // 73728

__device__ __forceinline__ void load_tile(uint32_t sbase,
                                          const __half* __restrict__ P,
                                          int r0, int k0, int pitch, int tid) {
#pragma unroll
    for (int i = 0; i < 4; i++) {
        int u = i * 256 + tid;
        int row = u >> 3, c16 = u & 7;
        const void* src = P + (size_t)(r0 + row) * pitch + k0 + c16 * 8;
        CP_ASYNC16(sbase + (row * PITCH + c16 * 8) * 2, src);
    }
}
__device__ __forceinline__ void load_stage2(uint32_t sbase,
                                            const __half* A, const __half* B,
                                            int m0, int n0, int k0, int ap, int bp, int tid) {
    load_tile(sbase,          A, m0, k0, ap, tid);
    load_tile(sbase + TILE_B, B, n0, k0, bp, tid);
}

#define MMA(acc, a, b0, b1) \
    asm volatile("mma.sync.aligned.m16n8k16.row.col.f32.f16.f16.f32 " \
        "{%0,%1,%2,%3}, {%4,%5,%6,%7}, {%8,%9}, {%0,%1,%2,%3};" \
        : "+f"((acc)[0]), "+f"((acc)[1]), "+f"((acc)[2]), "+f"((acc)[3]) \
        : "r"((a)[0]), "r"((a)[1]), "r"((a)[2]), "r"((a)[3]), "r"(b0), "r"(b1))

__device__ __forceinline__ void compute_chunk(uint32_t sbase, int wm, int wn, int lane,
                                              float acc[4][4][4]) {
    uint32_t sA = sbase, sB = sbase + TILE_B;
#pragma unroll
    for (int kk = 0; kk < 4; kk++) {
        uint32_t a[4][4], bb[2][4];
#pragma unroll
        for (int mt = 0; mt < 4; mt++) {
            uint32_t off = ((wm * 64 + mt * 16 + (lane & 15)) * PITCH
                            + kk * 16 + (lane >> 4) * 8) * 2;
            asm volatile("ldmatrix.sync.aligned.m8n8.x4.shared.b16 {%0,%1,%2,%3}, [%4];"
                : "=r"(a[mt][0]), "=r"(a[mt][1]), "=r"(a[mt][2]), "=r"(a[mt][3])
                : "r"(sA + off));
        }
#pragma unroll
        for (int nb = 0; nb < 2; nb++) {
            uint32_t off = ((wn * 32 + nb * 16 + (lane & 15)) * PITCH
                            + kk * 16 + (lane >> 4) * 8) * 2;
            asm volatile("ldmatrix.sync.aligned.m8n8.x4.shared.b16 {%0,%1,%2,%3}, [%4];"
                : "=r"(bb[nb][0]), "=r"(bb[nb][1]), "=r"(bb[nb][2]), "=r"(bb[nb][3])
                : "r"(sB + off));
        }
#pragma unroll
        for (int mt = 0; mt < 4; mt++)
#pragma unroll
            for (int nt = 0; nt < 4; nt++) {
                int hb = nt >> 1, lb = nt & 1;
                MMA(acc[mt][nt], a[mt], bb[hb][lb], bb[hb][2 + lb]);
            }
    }
}

// ---------------- GEMM1 ------------------------------------------------------
// grid (64, 2), block 256
__global__ __launch_bounds__(256) void k_gemm1(const float* __restrict__ b_up) {
    extern __shared__ char smem[];
    uint32_t sb = smem_u32(smem);
    int tid = threadIdx.x, lane = tid & 31, wid = tid >> 5;
    int wm = wid & 1, wn = wid >> 1;
    int bx = blockIdx.x, by = blockIdx.y;
    float acc[4][4][4];
#pragma unroll
    for (int i = 0; i < 4; i++)
#pragma unroll
        for (int j = 0; j < 4; j++)
#pragma unroll
            for (int k = 0; k < 4; k++) acc[i][j][k] = 0.f;

    const int C = 16;
    load_stage2(sb, g_ahi, g_wuphi, by * 128, bx * 128, 0, 1024, 1024, tid);
    CP_COMMIT();
    for (int c = 0; c < C; c++) {
        if (c + 1 < C)
            load_stage2(sb + ((c + 1) & 1) * STG2, g_ahi, g_wuphi,
                        by * 128, bx * 128, (c + 1) * 64, 1024, 1024, tid);
        CP_COMMIT();
        CP_WAIT1();
        __syncthreads();
        compute_chunk(sb + (c & 1) * STG2, wm, wn, lane, acc);
        __syncthreads();
    }

#pragma unroll
    for (int mt = 0; mt < 4; mt++) {
        int r0 = by * 128 + wm * 64 + mt * 16 + (lane >> 2);
#pragma unroll
        for (int nt = 0; nt < 4; nt++) {
            int fc = bx * 64 + wn * 16 + nt * 4 + (lane & 3);
            float bg = b_up[fc], bv = b_up[4096 + fc];
            float f0 = sinf(acc[mt][nt][0] + bg) * (acc[mt][nt][1] + bv);
            float f1 = sinf(acc[mt][nt][2] + bg) * (acc[mt][nt][3] + bv);
            size_t o0 = (size_t)r0 * 4096 + fc;
            size_t o1 = o0 + (size_t)8 * 4096;
            g_fhi[o0] = __float2half(f0);
            g_fhi[o1] = __float2half(f1);
        }
    }
}

// ---------------- GEMM2 + fused finisher (+state LN1 partials) ---------------
// grid (8, 2, 8), block 256
__global__ __launch_bounds__(256) void k_gemm2(const float* __restrict__ b_down,
                                               float* __restrict__ out, int step) {
    extern __shared__ char smem[];
    uint32_t sb = smem_u32(smem);
    int tid = threadIdx.x, lane = tid & 31, wid = tid >> 5;
    int wm = wid & 1, wn = wid >> 1;
    int bx = blockIdx.x, by = blockIdx.y, bz = blockIdx.z;
    float acc[4][4][4];
#pragma unroll
    for (int i = 0; i < 4; i++)
#pragma unroll
        for (int j = 0; j < 4; j++)
#pragma unroll
            for (int k = 0; k < 4; k++) acc[i][j][k] = 0.f;

    const int C = 8;
    load_stage2(sb, g_fhi, g_wdnhi, by * 128, bx * 128, bz * 512, 4096, 4096, tid);
    CP_COMMIT();
    for (int c = 0; c < C; c++) {
        if (c + 1 < C)
            load_stage2(sb + ((c + 1) & 1) * STG2, g_fhi, g_wdnhi,
                        by * 128, bx * 128, bz * 512 + (c + 1) * 64, 4096, 4096, tid);
        CP_COMMIT();
        CP_WAIT1();
        __syncthreads();
        compute_chunk(sb + (c & 1) * STG2, wm, wn, lane, acc);
        __syncthreads();
    }

#pragma unroll
    for (int mt = 0; mt < 4; mt++) {
        int r0 = by * 128 + wm * 64 + mt * 16 + (lane >> 2);
#pragma unroll
        for (int nt = 0; nt < 4; nt++) {
            int col = bx * 128 + wn * 32 + nt * 8 + (lane & 3) * 2;
            float* op = g_opart + ((size_t)(bz * 256) + r0) * 1024 + col;
            *(float2*)op = make_float2(acc[mt][nt][0], acc[mt][nt][1]);
            *(float2*)(op + (size_t)8 * 1024) = make_float2(acc[mt][nt][2], acc[mt][nt][3]);
        }
    }

    // ---- split-K finisher: 8th-arriving CTA per (bx,by) ----
    __threadfence();
    __shared__ int s_last;
    if (tid == 0) {
        int old;
        asm volatile("atom.add.release.gpu.s32 %0, [%1], 1;"
                     : "=r"(old) : "l"(&g_cnt[by * 8 + bx]) : "memory");
        s_last = (old == 7);
    }
    __syncthreads();
    if (s_last) {
        __threadfence();
#pragma unroll
        for (int i = 0; i < 16; i++) {
            int u = i * 256 + tid;
            int r = u >> 5, c4 = (u & 31) * 4;
            int gm = by * 128 + r;
            int col = bx * 128 + c4;
            float4 a = *(const float4*)(g_opart + ((size_t)gm << 10) + col);
#pragma unroll
            for (int s = 1; s < 8; s++) {
                float4 p = *(const float4*)(g_opart + ((size_t)((s << 8) + gm) << 10) + col);
                a.x += p.x; a.y += p.y; a.z += p.z; a.w += p.w;
            }
            float4 bd = *(const float4*)(b_down + col);
            float4 r2 = *(const float4*)(g_res2 + ((size_t)gm << 10) + col);
            a.x += bd.x + r2.x; a.y += bd.y + r2.y;
            a.z += bd.z + r2.z; a.w += bd.w + r2.w;
            int b = gm >> 6, t = gm & 63;
            float* dst = (t < 32)
                ? out + ((size_t)(b * T_TOK + step * 32 + t) << 10) + col
                : g_state + ((b * 32 + (t - 32)) << 10) + col;
            *(float4*)dst = a;
            // LN1 partial stats for rows that become next step's state
            float s = a.x + a.y + a.z + a.w;
            float q = a.x * a.x + a.y * a.y + a.z * a.z + a.w * a.w;
            s = warp_sum(s); q = warp_sum(q);
            if ((tid & 31) == 0) {
                g_spart[gm][bx][0] = s;
                g_spart[gm][bx][1] = q;
            }
        }
        __syncthreads();
        if (tid == 0) g_cnt[by * 8 + bx] = 0;
    }
}

// ---------------- host launcher ----------------------------------------------
extern "C" void kernel_launch(void* const* d_in, const int* in_sizes, int n_in,
                              void* d_out, int out_size) {
    const float* x    = (const float*)d_in[0];
    const float* ln1w = (const float*)d_in[1];
    const float* ln1b = (const float*)d_in[2];
    const float* wf1  = (const float*)d_in[3];
    const float* wf2  = (const float*)d_in[4];
    const float* ln2w = (const float*)d_in[5];
    const float* ln2b = (const float*)d_in[6];
    const float* w_up = (const float*)d_in[7];
    const float* b_up = (const float*)d_in[8];
    const float* w_dn = (const float*)d_in[9];
    const float* b_dn = (const float*)d_in[10];
    float* out = (float*)d_out;

    cudaFuncSetAttribute(k_gemm1, cudaFuncAttributeMaxDynamicSharedMemorySize, SMEM_TOT);
    cudaFuncSetAttribute(k_gemm2, cudaFuncAttributeMaxDynamicSharedMemorySize, SMEM_TOT);

    k_init_M<<<16, 256>>>(wf1, wf2);
    k_init_state<<<128, 256>>>(x);
    k_xstats<<<dim3(XPAD, B_SZ), 256>>>(x);
    k_conv_wup<<<8192, 256>>>(w_up);
    k_conv_wdn<<<1024, 256>>>(w_dn);

    for (int i = 0; i < NSTEP; i++) {
        k_fft<<<dim3(64, 4), 256>>>(x, ln1w, ln1b, ln2w, ln2b, i);
        k_gemm1<<<dim3(64, 2), 256, SMEM_TOT>>>(b_up);
        k_gemm2<<<dim3(8, 2, 8), 256, SMEM_TOT>>>(b_dn, out, i);
    }
}